// round 13
// baseline (speedup 1.0000x reference)
#include <cuda_runtime.h>
#include <math.h>

// Problem constants (fixed shapes from reference)
#define HH 224
#define WW 224
#define CC 3
#define LL 256            // B*F = 8*32
#define NOISE_LEN 766     // 3L-2
#define WIN 511           // 2L-1
#define FRAME_FLOATS (HH * WW * CC)   // 150528

// Per-frame 3x3 matrices (row-major), produced by kernel 1, consumed by kernel 2.
__device__ float g_M[LL * 9];

// ---------------------------------------------------------------------------
// Kernel 1: fused smoothing + matrix assembly. One block per frame, 128 thr.
// Signals dependent launch as soon as its g_M writes are done (PDL).
// ---------------------------------------------------------------------------
__global__ __launch_bounds__(128) void vrp_matrices(const float* __restrict__ noise,
                                                    const float* __restrict__ basis) {
    __shared__ float wv_sh[4];
    __shared__ double vmax[4];
    __shared__ double wp_sh[9];
    __shared__ float wsum_sh;

    const int tid = threadIdx.x;
    const int frame = blockIdx.x;
    const int warp = tid >> 5;
    const int lane = tid & 31;

    float sq[8];
    sq[0] = 1.1f;
    #pragma unroll
    for (int b = 1; b < 8; ++b) sq[b] = sq[b - 1] * sq[b - 1];

    const float* nr = noise + warp * NOISE_LEN + frame;
    float dot = 0.f, wsum = 0.f;
    for (int k = lane; k < WIN; k += 32) {
        const int e = (k < LL) ? k : (2 * LL - 2 - k);
        float p = 1.0f;
        #pragma unroll
        for (int b = 0; b < 8; ++b)
            if ((e >> b) & 1) p *= sq[b];
        dot = fmaf(__ldg(nr + k), p, dot);
        wsum += p;
    }
    #pragma unroll
    for (int off = 16; off > 0; off >>= 1) {
        dot  += __shfl_down_sync(0xffffffffu, dot, off);
        wsum += __shfl_down_sync(0xffffffffu, wsum, off);
    }
    if (lane == 0) {
        wv_sh[warp] = dot;
        if (warp == 0) wsum_sh = wsum;
    }
    __syncthreads();

    if (tid < 4) vmax[tid] = fmax((double)(wv_sh[tid] / wsum_sh), 0.0);
    __syncthreads();

    if (tid < 9) {
        const double s = vmax[0] + vmax[1] + vmax[2] + vmax[3];
        double wp = vmax[0] * (double)__ldg(basis + 0 + tid)
                  + vmax[1] * (double)__ldg(basis + 9 + tid)
                  + vmax[2] * (double)__ldg(basis + 18 + tid)
                  + vmax[3] * (double)__ldg(basis + 27 + tid);
        if (tid == 0 || tid == 4 || tid == 8) wp += 4.0 - s;
        wp_sh[tid] = wp;
    }
    __syncthreads();

    if (tid < 9) {
        const int row = tid / 3, col = tid % 3;
        const double inv223 = 1.0 / 223.0;
        double Trow, T2;
        if (col < 2) {
            Trow = wp_sh[row * 3 + col] * inv223;
            T2   = wp_sh[2 * 3 + col] * inv223;
        } else {
            Trow = -0.5 * wp_sh[row * 3 + 0] - 0.5 * wp_sh[row * 3 + 1] + wp_sh[row * 3 + 2];
            T2   = -0.5 * wp_sh[2 * 3 + 0] - 0.5 * wp_sh[2 * 3 + 1] + wp_sh[2 * 3 + 2];
        }
        const double Mel = (row < 2) ? (223.0 * Trow + 111.5 * T2) : T2;
        g_M[frame * 9 + tid] = (float)Mel;
    }

    asm volatile("griddepcontrol.launch_dependents;" ::: "memory");
}

// ---------------------------------------------------------------------------
// Kernel 2: per-pixel projective warp + bilinear sample.
// Reordered for latency overlap:
//   floor -> cheap OOB ballot -> clamps/addresses -> issue ALL loads ->
//   weight chain computed under the load shadow -> blend (weight-then-shift).
// ---------------------------------------------------------------------------
__global__ __launch_bounds__(256) void vrp_warp_bilinear(const float* __restrict__ x,
                                                         float* __restrict__ out) {
    __shared__ float Ms[9];
    __shared__ __align__(16) float stage[8][96];   // per-warp output staging

    const int l = blockIdx.z;
    const int wy8 = threadIdx.y;          // warp id in block (row within tile)
    const int lane = threadIdx.x;
    const int c = blockIdx.x * 32 + lane;
    const int r = blockIdx.y * 8 + wy8;

    asm volatile("griddepcontrol.wait;" ::: "memory");

    if (wy8 == 0 && lane < 9) Ms[lane] = g_M[l * 9 + lane];
    __syncthreads();

    const float fc = (float)c, fr = (float)r;
    const float pz = fmaf(Ms[6], fc, fmaf(Ms[7], fr, Ms[8]));
    const float inv = __fdividef(1.f, pz);
    const float sx = fmaf(Ms[0], fc, fmaf(Ms[1], fr, Ms[2])) * inv;
    const float sy = fmaf(Ms[3], fc, fmaf(Ms[4], fr, Ms[5])) * inv;

    const float x0f = floorf(sx), y0f = floorf(sy);

    // Cheap OOB predicate (equivalent to weight-sum > 0; NaN-safe: false).
    const bool any = (x0f >= -1.f) && (x0f <= 223.f) &&
                     (y0f >= -1.f) && (y0f <= 223.f);

    float acc0 = 0.f, acc1 = 0.f, acc2 = 0.f;

    if (__any_sync(0xffffffffu, any)) {
        // --- addresses + loads FIRST (weights computed under load shadow) ---
        const int x0 = (int)x0f;
        const int xb = min(max(x0, 0), WW - 2);
        const int y0c = min(max((int)y0f, -1), HH - 1);
        const int yT = max(y0c, 0);
        const int yB = min(y0c + 1, HH - 1);

        const float* img = x + (size_t)l * FRAME_FLOATS;
        const float4* img4 = (const float4*)img;

        const int fT = (yT * WW + xb) * 3;
        const int fB = (yB * WW + xb) * 3;
        const int aT = fT >> 2;
        const int aB = fB >> 2;
        const int s = fT & 3;               // same for both rows (672 % 4 == 0)

        const float4 T0 = __ldg(img4 + aT);
        const float4 T1 = __ldg(img4 + aT + 1);
        const float4 B0 = __ldg(img4 + aB);
        const float4 B1 = __ldg(img4 + aB + 1);
        float dT8 = 0.f, dB8 = 0.f;
        if (s == 3) {
            dT8 = __ldg(img + (size_t)(aT + 2) * 4);
            dB8 = __ldg(img + (size_t)(aB + 2) * 4);
        }

        // --- weight chain: independent of loaded data ---
        const float wx = sx - x0f, wy = sy - y0f;
        const float omwx = 1.f - wx, omwy = 1.f - wy;

        const float gyT = (y0f >= 0.f  && y0f <= 223.f) ? omwy : 0.f;
        const float gyB = (y0f >= -1.f && y0f <= 222.f) ? wy   : 0.f;

        const bool pin = (x0f >= 0.f) && (x0f <= 222.f);
        const float h0 = pin ? omwx : ((x0f == -1.f)  ? wx   : 0.f);
        const float h1 = pin ? wx   : ((x0f == 223.f) ? omwx : 0.f);

        const float wT0 = gyT * h0, wT1 = gyT * h1;
        const float wB0 = gyB * h0, wB1 = gyB * h1;

        // --- blend rows, then single shift: res_c = R_{c+s} ---
        const float R0 = fmaf(wT0, T0.x, fmaf(wB0, B0.x, fmaf(wT1, T0.w, wB1 * B0.w)));
        const float R1 = fmaf(wT0, T0.y, fmaf(wB0, B0.y, fmaf(wT1, T1.x, wB1 * B1.x)));
        const float R2 = fmaf(wT0, T0.z, fmaf(wB0, B0.z, fmaf(wT1, T1.y, wB1 * B1.y)));
        const float R3 = fmaf(wT0, T0.w, fmaf(wB0, B0.w, fmaf(wT1, T1.z, wB1 * B1.z)));
        const float R4 = fmaf(wT0, T1.x, fmaf(wB0, B1.x, fmaf(wT1, T1.w, wB1 * B1.w)));
        const float R5 = fmaf(wT0, T1.y, fmaf(wB0, B1.y, fmaf(wT1, dT8, wB1 * dB8)));

        const bool b2 = (s & 2) != 0;
        const bool b1 = (s & 1) != 0;
        const float m0 = b2 ? R2 : R0;
        const float m1 = b2 ? R3 : R1;
        const float m2 = b2 ? R4 : R2;
        const float m3 = b2 ? R5 : R3;
        acc0 = b1 ? m1 : m0;
        acc1 = b1 ? m2 : m1;
        acc2 = b1 ? m3 : m2;
    }

    // Repack through shared: warp-local, then 24 lanes emit STG.128.
    stage[wy8][lane * 3 + 0] = acc0;
    stage[wy8][lane * 3 + 1] = acc1;
    stage[wy8][lane * 3 + 2] = acc2;
    __syncwarp();

    if (lane < 24) {
        const float4 v = ((const float4*)stage[wy8])[lane];
        float4* obase = (float4*)(out + ((size_t)(l * HH + r) * WW + blockIdx.x * 32) * CC);
        obase[lane] = v;
    }
}

// ---------------------------------------------------------------------------
// Launch: kernel1 normally; kernel2 with programmatic stream serialization.
// ---------------------------------------------------------------------------
extern "C" void kernel_launch(void* const* d_in, const int* in_sizes, int n_in,
                              void* d_out, int out_size) {
    const float* x     = (const float*)d_in[0];
    const float* noise = (const float*)d_in[1];
    const float* basis = (const float*)d_in[2];
    float* out = (float*)d_out;

    vrp_matrices<<<LL, 128>>>(noise, basis);

    dim3 block(32, 8, 1);
    dim3 grid(WW / 32, HH / 8, LL);  // 7 x 28 x 256

    cudaLaunchConfig_t cfg = {};
    cfg.gridDim = grid;
    cfg.blockDim = block;
    cfg.dynamicSmemBytes = 0;
    cudaLaunchAttribute attrs[1];
    attrs[0].id = cudaLaunchAttributeProgrammaticStreamSerialization;
    attrs[0].val.programmaticStreamSerializationAllowed = 1;
    cfg.attrs = attrs;
    cfg.numAttrs = 1;
    cudaLaunchKernelEx(&cfg, vrp_warp_bilinear, x, out);
}

// round 14
// speedup vs baseline: 1.0220x; 1.0220x over previous
#include <cuda_runtime.h>
#include <math.h>

// Problem constants (fixed shapes from reference)
#define HH 224
#define WW 224
#define CC 3
#define LL 256            // B*F = 8*32
#define NOISE_LEN 766     // 3L-2
#define WIN 511           // 2L-1
#define FRAME_FLOATS (HH * WW * CC)   // 150528

// Per-frame 3x3 matrices (row-major), produced by kernel 1, consumed by kernel 2.
__device__ float g_M[LL * 9];

// ---------------------------------------------------------------------------
// Kernel 1: fused smoothing + matrix assembly. One block per frame, 128 thr.
// ---------------------------------------------------------------------------
__global__ __launch_bounds__(128) void vrp_matrices(const float* __restrict__ noise,
                                                    const float* __restrict__ basis) {
    __shared__ float wv_sh[4];
    __shared__ double vmax[4];
    __shared__ double wp_sh[9];
    __shared__ float wsum_sh;

    const int tid = threadIdx.x;
    const int frame = blockIdx.x;
    const int warp = tid >> 5;
    const int lane = tid & 31;

    float sq[8];
    sq[0] = 1.1f;
    #pragma unroll
    for (int b = 1; b < 8; ++b) sq[b] = sq[b - 1] * sq[b - 1];

    const float* nr = noise + warp * NOISE_LEN + frame;
    float dot = 0.f, wsum = 0.f;
    for (int k = lane; k < WIN; k += 32) {
        const int e = (k < LL) ? k : (2 * LL - 2 - k);
        float p = 1.0f;
        #pragma unroll
        for (int b = 0; b < 8; ++b)
            if ((e >> b) & 1) p *= sq[b];
        dot = fmaf(__ldg(nr + k), p, dot);
        wsum += p;
    }
    #pragma unroll
    for (int off = 16; off > 0; off >>= 1) {
        dot  += __shfl_down_sync(0xffffffffu, dot, off);
        wsum += __shfl_down_sync(0xffffffffu, wsum, off);
    }
    if (lane == 0) {
        wv_sh[warp] = dot;
        if (warp == 0) wsum_sh = wsum;
    }
    __syncthreads();

    if (tid < 4) vmax[tid] = fmax((double)(wv_sh[tid] / wsum_sh), 0.0);
    __syncthreads();

    if (tid < 9) {
        const double s = vmax[0] + vmax[1] + vmax[2] + vmax[3];
        double wp = vmax[0] * (double)__ldg(basis + 0 + tid)
                  + vmax[1] * (double)__ldg(basis + 9 + tid)
                  + vmax[2] * (double)__ldg(basis + 18 + tid)
                  + vmax[3] * (double)__ldg(basis + 27 + tid);
        if (tid == 0 || tid == 4 || tid == 8) wp += 4.0 - s;
        wp_sh[tid] = wp;
    }
    __syncthreads();

    if (tid < 9) {
        const int row = tid / 3, col = tid % 3;
        const double inv223 = 1.0 / 223.0;
        double Trow, T2;
        if (col < 2) {
            Trow = wp_sh[row * 3 + col] * inv223;
            T2   = wp_sh[2 * 3 + col] * inv223;
        } else {
            Trow = -0.5 * wp_sh[row * 3 + 0] - 0.5 * wp_sh[row * 3 + 1] + wp_sh[row * 3 + 2];
            T2   = -0.5 * wp_sh[2 * 3 + 0] - 0.5 * wp_sh[2 * 3 + 1] + wp_sh[2 * 3 + 2];
        }
        const double Mel = (row < 2) ? (223.0 * Trow + 111.5 * T2) : T2;
        g_M[frame * 9 + tid] = (float)Mel;
    }

    asm volatile("griddepcontrol.launch_dependents;" ::: "memory");
}

// ---------------------------------------------------------------------------
// Kernel 2: per-pixel projective warp + bilinear sample (R11 body).
// Streaming (evict-first) output stores so the write stream doesn't evict
// the x gather working set from L2.
// ---------------------------------------------------------------------------
__global__ __launch_bounds__(256) void vrp_warp_bilinear(const float* __restrict__ x,
                                                         float* __restrict__ out) {
    __shared__ float Ms[9];
    __shared__ __align__(16) float stage[8][96];   // per-warp output staging

    const int l = blockIdx.z;
    const int wy8 = threadIdx.y;          // warp id in block (row within tile)
    const int lane = threadIdx.x;
    const int c = blockIdx.x * 32 + lane;
    const int r = blockIdx.y * 8 + wy8;

    asm volatile("griddepcontrol.wait;" ::: "memory");

    if (wy8 == 0 && lane < 9) Ms[lane] = g_M[l * 9 + lane];
    __syncthreads();

    const float fc = (float)c, fr = (float)r;
    const float pz = fmaf(Ms[6], fc, fmaf(Ms[7], fr, Ms[8]));
    const float inv = __fdividef(1.f, pz);
    const float sx = fmaf(Ms[0], fc, fmaf(Ms[1], fr, Ms[2])) * inv;
    const float sy = fmaf(Ms[3], fc, fmaf(Ms[4], fr, Ms[5])) * inv;

    const float x0f = floorf(sx), y0f = floorf(sy);
    const float wx = sx - x0f, wy = sy - y0f;
    const float omwx = 1.f - wx, omwy = 1.f - wy;

    // y-side row weights (0 if row invalid; NaN-safe: compares false on NaN)
    const float gyT = (y0f >= 0.f  && y0f <= 223.f) ? omwy : 0.f;
    const float gyB = (y0f >= -1.f && y0f <= 222.f) ? wy   : 0.f;

    // x-side slot weights; slot0 = col xb, slot1 = col xb+1, xb = clamp(x0,0,222)
    const bool pin = (x0f >= 0.f) && (x0f <= 222.f);
    const float h0 = pin ? omwx : ((x0f == -1.f)  ? wx   : 0.f);
    const float h1 = pin ? wx   : ((x0f == 223.f) ? omwx : 0.f);

    const float wT0 = gyT * h0, wT1 = gyT * h1;
    const float wB0 = gyB * h0, wB1 = gyB * h1;

    float acc0 = 0.f, acc1 = 0.f, acc2 = 0.f;

    const bool any = (wT0 + wT1 + wB0 + wB1) > 0.f;   // weights are >= 0
    if (__any_sync(0xffffffffu, any)) {
        const int x0 = (int)x0f;                       // weights gate saturation cases
        const int xb = min(max(x0, 0), WW - 2);
        const int y0c = min(max((int)y0f, -1), HH - 1);
        const int yT = max(y0c, 0);
        const int yB = min(y0c + 1, HH - 1);

        const float* img = x + (size_t)l * FRAME_FLOATS;
        const float4* img4 = (const float4*)img;

        const int fT = (yT * WW + xb) * 3;
        const int fB = (yB * WW + xb) * 3;
        const int s = fT & 3;               // same for both rows (672 % 4 == 0)
        const bool b2 = (s & 2) != 0;
        const bool b1 = (s & 1) != 0;
        const bool need8 = (s == 3);

        #pragma unroll
        for (int rowi = 0; rowi < 2; ++rowi) {
            const int f = rowi ? fB : fT;
            const float w0s = rowi ? wB0 : wT0;
            const float w1s = rowi ? wB1 : wT1;

            const int a = f >> 2;
            const float4 v0 = __ldg(img4 + a);
            const float4 v1 = __ldg(img4 + a + 1);
            const float d8 = need8 ? __ldg(img + (size_t)(a + 2) * 4) : 0.f;

            // e[j] = d[s+j], d = {v0.x..w, v1.x..w, d8}
            const float t0 = b2 ? v0.z : v0.x;
            const float t1 = b2 ? v0.w : v0.y;
            const float t2 = b2 ? v1.x : v0.z;
            const float t3 = b2 ? v1.y : v0.w;
            const float t4 = b2 ? v1.z : v1.x;
            const float t5 = b2 ? v1.w : v1.y;
            const float t6 = b2 ? d8   : v1.z;

            const float e0 = b1 ? t1 : t0;
            const float e1 = b1 ? t2 : t1;
            const float e2 = b1 ? t3 : t2;
            const float e3 = b1 ? t4 : t3;
            const float e4 = b1 ? t5 : t4;
            const float e5 = b1 ? t6 : t5;

            acc0 = fmaf(w0s, e0, acc0);
            acc1 = fmaf(w0s, e1, acc1);
            acc2 = fmaf(w0s, e2, acc2);
            acc0 = fmaf(w1s, e3, acc0);
            acc1 = fmaf(w1s, e4, acc1);
            acc2 = fmaf(w1s, e5, acc2);
        }
    }

    // Repack through shared: warp-local, then 24 lanes emit streaming STG.128.
    stage[wy8][lane * 3 + 0] = acc0;
    stage[wy8][lane * 3 + 1] = acc1;
    stage[wy8][lane * 3 + 2] = acc2;
    __syncwarp();

    if (lane < 24) {
        const float4 v = ((const float4*)stage[wy8])[lane];
        float4* obase = (float4*)(out + ((size_t)(l * HH + r) * WW + blockIdx.x * 32) * CC);
        __stcs(obase + lane, v);   // evict-first: don't pollute L2 read set
    }
}

// ---------------------------------------------------------------------------
// Launch: kernel1 normally; kernel2 with programmatic stream serialization.
// ---------------------------------------------------------------------------
extern "C" void kernel_launch(void* const* d_in, const int* in_sizes, int n_in,
                              void* d_out, int out_size) {
    const float* x     = (const float*)d_in[0];
    const float* noise = (const float*)d_in[1];
    const float* basis = (const float*)d_in[2];
    float* out = (float*)d_out;

    vrp_matrices<<<LL, 128>>>(noise, basis);

    dim3 block(32, 8, 1);
    dim3 grid(WW / 32, HH / 8, LL);  // 7 x 28 x 256

    cudaLaunchConfig_t cfg = {};
    cfg.gridDim = grid;
    cfg.blockDim = block;
    cfg.dynamicSmemBytes = 0;
    cudaLaunchAttribute attrs[1];
    attrs[0].id = cudaLaunchAttributeProgrammaticStreamSerialization;
    attrs[0].val.programmaticStreamSerializationAllowed = 1;
    cfg.attrs = attrs;
    cfg.numAttrs = 1;
    cudaLaunchKernelEx(&cfg, vrp_warp_bilinear, x, out);
}